// round 1
// baseline (speedup 1.0000x reference)
#include <cuda_runtime.h>

// PositionalEncodingLayer: out[b,t,d] = X[b,t,d] + pe[t,d]
//   pe[t, 2i]   = sin(t / 10000^(2i/d))
//   pe[t, 2i+1] = cos(t / 10000^(2i/d))
// B=8, T=4096, D=1024, fp32.
//
// Strategy: memory-bound broadcast add.
//  - float4 vectorization, one thread per (row, 4-column chunk)
//  - trig computed once per (t, column-pair) and reused across all 8 batches
//  - TPT consecutive rows per thread advanced by a sin/cos rotation recurrence
//    (4 FMA per step) instead of fresh sincosf per row

constexpr int Bn  = 8;
constexpr int Tn  = 4096;
constexpr int Dn  = 1024;
constexpr int C4  = Dn / 4;            // 256 float4 chunks per row
constexpr int TPT = 4;                 // rows handled per thread
constexpr int PLANE4 = Tn * C4;        // float4 per batch plane (1,048,576)

__global__ __launch_bounds__(C4)
void pe_add_kernel(const float4* __restrict__ X, float4* __restrict__ O)
{
    const int j  = threadIdx.x;            // column chunk 0..255 (cols 4j..4j+3)
    const int t0 = blockIdx.x * TPT;       // base row

    // inv_freq_i = 10000^(-2i/D) = exp2(-i * 2*log2(10000)/D)
    const float k  = 0.02595256306250292f; // 2*log2(10000)/1024
    const float i0 = (float)(2 * j);
    const float i1 = i0 + 1.0f;
    const float f0 = exp2f(-i0 * k);
    const float f1 = exp2f(-i1 * k);

    // initial sin/cos at row t0, plus per-row rotation deltas
    float s0, c0, s1, c1;
    sincosf((float)t0 * f0, &s0, &c0);
    sincosf((float)t0 * f1, &s1, &c1);
    float sd0, cd0, sd1, cd1;
    sincosf(f0, &sd0, &cd0);
    sincosf(f1, &sd1, &cd1);

    int base = t0 * C4 + j;                // fits in int32 (max 8M)

    #pragma unroll
    for (int tt = 0; tt < TPT; ++tt) {
        const float4 pe = make_float4(s0, c0, s1, c1);
        const int idx = base + tt * C4;
        #pragma unroll
        for (int b = 0; b < Bn; ++b) {
            const int p = idx + b * PLANE4;
            float4 x = X[p];
            x.x += pe.x; x.y += pe.y; x.z += pe.z; x.w += pe.w;
            O[p] = x;
        }
        // rotate: angle += inv_freq
        const float ns0 = fmaf(s0, cd0,  c0 * sd0);
        const float nc0 = fmaf(c0, cd0, -s0 * sd0);
        const float ns1 = fmaf(s1, cd1,  c1 * sd1);
        const float nc1 = fmaf(c1, cd1, -s1 * sd1);
        s0 = ns0; c0 = nc0; s1 = ns1; c1 = nc1;
    }
}

extern "C" void kernel_launch(void* const* d_in, const int* in_sizes, int n_in,
                              void* d_out, int out_size)
{
    (void)in_sizes; (void)n_in; (void)out_size;
    const float4* X = (const float4*)d_in[0];
    float4*       O = (float4*)d_out;
    pe_add_kernel<<<Tn / TPT, C4>>>(X, O);
}

// round 2
// speedup vs baseline: 1.0388x; 1.0388x over previous
#include <cuda_runtime.h>

// PositionalEncodingLayer: out[b,t,d] = X[b,t,d] + pe[t,d]
//   pe[t, 2i]   = sin(t / 10000^(2i/d))
//   pe[t, 2i+1] = cos(t / 10000^(2i/d))
// B=8, T=4096, D=1024, fp32.
//
// Round 2: pure streaming form.
//  - one thread per (row t, 4-column chunk): grid=4096, block=256
//  - all 8 batch loads issued FIRST (MLP=8, overlaps DRAM latency with trig)
//  - fresh sincosf per thread (trig is <1% of the budget; the recurrence in
//    R1 cost 76 regs and capped occupancy at 32%)
//  - streaming cache hints on the zero-reuse load/store paths

constexpr int Bn  = 8;
constexpr int Tn  = 4096;
constexpr int Dn  = 1024;
constexpr int C4  = Dn / 4;            // 256 float4 chunks per row
constexpr int PLANE4 = Tn * C4;        // float4 per batch plane (1,048,576)

__global__ __launch_bounds__(C4)
void pe_add_kernel(const float4* __restrict__ X, float4* __restrict__ O)
{
    const int j = threadIdx.x;             // column chunk: cols 4j..4j+3
    const int t = blockIdx.x;              // row
    const int idx = t * C4 + j;            // fits in int32 (max 8M)

    // Issue all 8 loads up front — independent, front-batched MLP.
    float4 x[Bn];
    #pragma unroll
    for (int b = 0; b < Bn; ++b)
        x[b] = __ldcs(&X[idx + b * PLANE4]);

    // pe for this thread's 4 columns (pair 2j -> sin/cos, pair 2j+1 -> sin/cos)
    // inv_freq_i = 10000^(-2i/D) = exp2(-i * 2*log2(10000)/D)
    const float k  = 0.02595256306250292f; // 2*log2(10000)/1024
    const float i0 = (float)(2 * j);
    const float f0 = exp2f(-i0 * k);
    const float f1 = exp2f(-(i0 + 1.0f) * k);
    float s0, c0, s1, c1;
    sincosf((float)t * f0, &s0, &c0);
    sincosf((float)t * f1, &s1, &c1);

    #pragma unroll
    for (int b = 0; b < Bn; ++b) {
        float4 v = x[b];
        v.x += s0; v.y += c0; v.z += s1; v.w += c1;
        __stcs(&O[idx + b * PLANE4], v);
    }
}

extern "C" void kernel_launch(void* const* d_in, const int* in_sizes, int n_in,
                              void* d_out, int out_size)
{
    (void)in_sizes; (void)n_in; (void)out_size;
    const float4* X = (const float4*)d_in[0];
    float4*       O = (float4*)d_out;
    pe_add_kernel<<<Tn, C4>>>(X, O);
}